// round 1
// baseline (speedup 1.0000x reference)
#include <cuda_runtime.h>
#include <cstdint>

#define NPTS 150000
#define BB 2
#define ROWS (BB*NPTS)          // 300000
#define CCH 64
#define DDIM 128
#define D3 (DDIM*DDIM*DDIM)     // 2097152
#define TILE 256
#define NTHR 256
#define HS 68                    // smem row stride (floats): 68*4B => bank offsets 0,4,8,12 for consecutive rows
#define NTILES ((ROWS + TILE - 1)/TILE)   // 1172
#define SROWS 512
#define EPSV 1e-4f
#define WSTRIDE (27*64*64)       // floats per conv layer weight

// dynamic smem layout (floats): W 4096 | scale 64 | bias 64 | dst 256(int) | src 256(int) | H TILE*HS
#define SMEM_BYTES ((4096 + 64 + 64 + TILE*HS) * 4 + 2*TILE*4)

// ---------------- scratch (device globals; no allocation allowed) ----------------
__device__ int   g_lut[BB*D3];
__device__ int2  g_pairs[26*ROWS];
__device__ int   g_cnt[26];
__device__ float g_sum[4*64];
__device__ float g_sqs[4*64];
__device__ float g_U[(size_t)ROWS*CCH];
__device__ float g_X[(size_t)ROWS*CCH];

// ---------------- packed fp32x2 helpers (Blackwell) ----------------
__device__ __forceinline__ void ffma2(unsigned long long &d, unsigned long long a, unsigned long long b) {
    asm("fma.rn.f32x2 %0, %1, %2, %0;" : "+l"(d) : "l"(a), "l"(b));
}
__device__ __forceinline__ unsigned long long dup2(float x) {
    unsigned long long r; unsigned int xi = __float_as_uint(x);
    asm("mov.b64 %0, {%1, %1};" : "=l"(r) : "r"(xi));
    return r;
}
__device__ __forceinline__ float2 unpk(unsigned long long u) {
    float2 f;
    asm("mov.b64 {%0, %1}, %2;" : "=f"(f.x), "=f"(f.y) : "l"(u));
    return f;
}

// ---------------- setup kernels ----------------
__global__ void k_init() {
    int i = blockIdx.x * blockDim.x + threadIdx.x;
    int stride = gridDim.x * blockDim.x;
    for (int v = i; v < BB*D3; v += stride) g_lut[v] = -1;
    if (i < 26) g_cnt[i] = 0;
    if (i < 4*64) { g_sum[i] = 0.f; g_sqs[i] = 0.f; }
}

__global__ void k_fill(const int* __restrict__ pos) {
    int i = blockIdx.x * blockDim.x + threadIdx.x;
    if (i >= ROWS) return;
    int b = i / NPTS;
    int x = pos[3*i], y = pos[3*i+1], z = pos[3*i+2];
    g_lut[b*D3 + (x*DDIM + y)*DDIM + z] = i;
}

__global__ void k_pairs(const int* __restrict__ pos) {
    int i = blockIdx.x * blockDim.x + threadIdx.x;
    if (i >= ROWS) return;                 // ROWS % 32 == 0 -> warps fully active or fully exited
    int b = i / NPTS;
    int px = pos[3*i], py = pos[3*i+1], pz = pos[3*i+2];
    const int lane = threadIdx.x & 31;
    const int* lut = g_lut + b*D3;
    #pragma unroll
    for (int k = 0; k < 27; k++) {
        if (k == 13) continue;             // center handled densely
        int x = px + k/9 - 1;
        int y = py + (k/3)%3 - 1;
        int z = pz + k%3 - 1;
        bool valid = ((unsigned)x < DDIM) && ((unsigned)y < DDIM) && ((unsigned)z < DDIM);
        int j = -1;
        if (valid) j = lut[(x*DDIM + y)*DDIM + z];
        valid = (j >= 0);
        unsigned m = __ballot_sync(0xffffffffu, valid);
        if (m == 0) continue;
        int kk = k - (k > 13 ? 1 : 0);
        int base = 0;
        int leader = __ffs(m) - 1;
        if (lane == leader) base = atomicAdd(&g_cnt[kk], __popc(m));
        base = __shfl_sync(0xffffffffu, base, leader);
        if (valid) {
            int off = __popc(m & ((1u << lane) - 1u));
            g_pairs[kk*ROWS + base + off] = make_int2(i, j);
        }
    }
}

// ---------------- BN statistics ----------------
__global__ void k_stats(const float* __restrict__ x, int slot) {
    __shared__ float ss[4][64];
    __shared__ float ss2[4][64];
    const int c = threadIdx.x & 63;
    const int rs = threadIdx.x >> 6;
    float s = 0.f, s2 = 0.f;
    int r = blockIdx.x * SROWS + rs;
    int rend = min(blockIdx.x * SROWS + SROWS, ROWS);
    for (; r < rend; r += 4) {
        float v = x[(size_t)r*64 + c];
        s += v;
        s2 = fmaf(v, v, s2);
    }
    ss[rs][c] = s; ss2[rs][c] = s2;
    __syncthreads();
    if (threadIdx.x < 64) {
        float t  = ss[0][c] + ss[1][c] + ss[2][c] + ss[3][c];
        float t2 = ss2[0][c] + ss2[1][c] + ss2[2][c] + ss2[3][c];
        atomicAdd(&g_sum[slot*64 + c], t);
        atomicAdd(&g_sqs[slot*64 + c], t2);
    }
}

// ---------------- fused BN+ReLU -> conv tile kernel ----------------
// TAPS=false: dense center tap over all rows; writes out (optionally += addsrc).
// TAPS=true : one off-center tap per blockIdx.y, compacted pair list, scatter via red.v4.
template<bool TAPS, bool ADD>
__global__ void __launch_bounds__(NTHR, 2)
k_conv(const float* __restrict__ in, const float* __restrict__ Wl,
       const float* __restrict__ gamma, const float* __restrict__ beta,
       int slot, const float* __restrict__ addsrc, float* __restrict__ out)
{
    const int tid = threadIdx.x;
    const int tileBase = blockIdx.x * TILE;
    const float* Wk;
    int kk = 0, cnt = 0;
    if (TAPS) {
        kk = blockIdx.y;
        cnt = g_cnt[kk];
        if (tileBase >= cnt) return;
        int k = kk + (kk >= 13 ? 1 : 0);
        Wk = Wl + k * 4096;
    } else {
        Wk = Wl + 13 * 4096;
    }

    extern __shared__ float smem[];
    float* sW     = smem;                    // 4096
    float* sScale = sW + 4096;               // 64
    float* sBias  = sScale + 64;             // 64
    int*   sDst   = (int*)(sBias + 64);      // 256
    int*   sSrc   = sDst + TILE;             // 256
    float* sH     = (float*)(sSrc + TILE);   // TILE*HS

    // derive BN scale/bias from raw sums (no separate finalize kernel)
    if (tid < 64) {
        const float inv = 1.0f / (float)ROWS;
        float mu  = g_sum[slot*64 + tid] * inv;
        float var = g_sqs[slot*64 + tid] * inv - mu*mu;
        float sc  = gamma[tid] * rsqrtf(var + EPSV);
        sScale[tid] = sc;
        sBias[tid]  = fmaf(-mu, sc, beta[tid]);
    }
    // stage W_k (16KB)
    #pragma unroll
    for (int v = tid; v < 1024; v += NTHR)
        ((float4*)sW)[v] = ((const float4*)Wk)[v];
    // entry lists
    if (TAPS) {
        int e = tileBase + tid;
        int2 pr = (e < cnt) ? g_pairs[kk*ROWS + e] : make_int2(-1, -1);
        sDst[tid] = pr.x; sSrc[tid] = pr.y;
    } else {
        int gr = tileBase + tid;
        int v = (gr < ROWS) ? gr : -1;
        sDst[tid] = v; sSrc[tid] = v;
    }
    __syncthreads();

    // gather rows + fused BN+ReLU into smem
    #pragma unroll
    for (int v = tid; v < TILE*16; v += NTHR) {
        int row = v >> 4, c4 = v & 15;
        int src = sSrc[row];
        float4 val = make_float4(0.f, 0.f, 0.f, 0.f);
        if (src >= 0) {
            float4 x = __ldg((const float4*)(in + (size_t)src*64) + c4);
            float4 s = ((const float4*)sScale)[c4];
            float4 b = ((const float4*)sBias)[c4];
            val.x = fmaxf(fmaf(x.x, s.x, b.x), 0.f);
            val.y = fmaxf(fmaf(x.y, s.y, b.y), 0.f);
            val.z = fmaxf(fmaf(x.z, s.z, b.z), 0.f);
            val.w = fmaxf(fmaf(x.w, s.w, b.w), 0.f);
        }
        *(float4*)(sH + row*HS + c4*4) = val;
    }
    __syncthreads();

    // register tile: each thread owns 8 rows x 8 channels, packed as f32x2 pairs
    const int cg = tid & 7;          // channel group: channels [8*cg, 8*cg+8)
    const int q  = (tid >> 3) & 3;   // row phase within warp
    const int wp = tid >> 5;         // warp id: rows [32*wp, 32*wp+32)
    unsigned long long acc[8][4];
    #pragma unroll
    for (int j = 0; j < 8; j++)
        #pragma unroll
        for (int c = 0; c < 4; c++) acc[j][c] = 0ull;

    const float* hb = sH + (wp*32 + q)*HS;
    const float* wb = sW + cg*8;
    #pragma unroll 4
    for (int cin = 0; cin < 64; cin++) {
        longlong2 w01 = *(const longlong2*)(wb + cin*64);
        longlong2 w23 = *(const longlong2*)(wb + cin*64 + 4);
        #pragma unroll
        for (int j = 0; j < 8; j++) {
            unsigned long long h2 = dup2(hb[j*4*HS + cin]);
            ffma2(acc[j][0], h2, (unsigned long long)w01.x);
            ffma2(acc[j][1], h2, (unsigned long long)w01.y);
            ffma2(acc[j][2], h2, (unsigned long long)w23.x);
            ffma2(acc[j][3], h2, (unsigned long long)w23.y);
        }
    }

    // epilogue
    #pragma unroll
    for (int j = 0; j < 8; j++) {
        int row = wp*32 + 4*j + q;
        int dst = sDst[row];
        if (dst < 0) continue;
        float* op = out + (size_t)dst*64 + cg*8;
        float2 a0 = unpk(acc[j][0]), a1 = unpk(acc[j][1]);
        float2 a2 = unpk(acc[j][2]), a3 = unpk(acc[j][3]);
        if (TAPS) {
            asm volatile("red.global.add.v4.f32 [%0], {%1,%2,%3,%4};"
                         :: "l"(op),   "f"(a0.x), "f"(a0.y), "f"(a1.x), "f"(a1.y) : "memory");
            asm volatile("red.global.add.v4.f32 [%0], {%1,%2,%3,%4};"
                         :: "l"(op+4), "f"(a2.x), "f"(a2.y), "f"(a3.x), "f"(a3.y) : "memory");
        } else {
            float4 r0 = make_float4(a0.x, a0.y, a1.x, a1.y);
            float4 r1 = make_float4(a2.x, a2.y, a3.x, a3.y);
            if (ADD) {
                const float4* ap = (const float4*)(addsrc + (size_t)dst*64 + cg*8);
                float4 b0 = ap[0], b1 = ap[1];
                r0.x += b0.x; r0.y += b0.y; r0.z += b0.z; r0.w += b0.w;
                r1.x += b1.x; r1.y += b1.y; r1.z += b1.z; r1.w += b1.w;
            }
            ((float4*)op)[0] = r0;
            ((float4*)op)[1] = r1;
        }
    }
}

// ---------------- launch ----------------
extern "C" void kernel_launch(void* const* d_in, const int* in_sizes, int n_in,
                              void* d_out, int out_size) {
    const float* feats = (const float*)d_in[0];
    const float* Ws    = (const float*)d_in[1];
    const float* gam   = (const float*)d_in[2];
    const float* bet   = (const float*)d_in[3];
    const int*   pos   = (const int*)d_in[4];
    float* out = (float*)d_out;

    cudaFuncSetAttribute(k_conv<false,false>, cudaFuncAttributeMaxDynamicSharedMemorySize, SMEM_BYTES);
    cudaFuncSetAttribute(k_conv<false,true>,  cudaFuncAttributeMaxDynamicSharedMemorySize, SMEM_BYTES);
    cudaFuncSetAttribute(k_conv<true,false>,  cudaFuncAttributeMaxDynamicSharedMemorySize, SMEM_BYTES);

    float *pU, *pX;
    cudaGetSymbolAddress((void**)&pU, g_U);
    cudaGetSymbolAddress((void**)&pX, g_X);

    const int gPts   = (ROWS + 255) / 256;           // 1172
    const int gStats = (ROWS + SROWS - 1) / SROWS;   // 586
    dim3 gTap(NTILES, 26);

    k_init <<<2048, 256>>>();
    k_fill <<<gPts, 256>>>(pos);
    k_pairs<<<gPts, 256>>>(pos);

    // ---- residual block 0 ----
    k_stats<<<gStats, 256>>>(feats, 0);
    k_conv<false,false><<<NTILES, NTHR, SMEM_BYTES>>>(feats, Ws + 0*WSTRIDE, gam + 0,   bet + 0,   0, nullptr, pU);
    k_conv<true, false><<<gTap,   NTHR, SMEM_BYTES>>>(feats, Ws + 0*WSTRIDE, gam + 0,   bet + 0,   0, nullptr, pU);
    k_stats<<<gStats, 256>>>(pU, 1);
    k_conv<false,true ><<<NTILES, NTHR, SMEM_BYTES>>>(pU,    Ws + 1*WSTRIDE, gam + 64,  bet + 64,  1, feats,   pX);
    k_conv<true, false><<<gTap,   NTHR, SMEM_BYTES>>>(pU,    Ws + 1*WSTRIDE, gam + 64,  bet + 64,  1, nullptr, pX);

    // ---- residual block 1 ----
    k_stats<<<gStats, 256>>>(pX, 2);
    k_conv<false,false><<<NTILES, NTHR, SMEM_BYTES>>>(pX,    Ws + 2*WSTRIDE, gam + 128, bet + 128, 2, nullptr, pU);
    k_conv<true, false><<<gTap,   NTHR, SMEM_BYTES>>>(pX,    Ws + 2*WSTRIDE, gam + 128, bet + 128, 2, nullptr, pU);
    k_stats<<<gStats, 256>>>(pU, 3);
    k_conv<false,true ><<<NTILES, NTHR, SMEM_BYTES>>>(pU,    Ws + 3*WSTRIDE, gam + 192, bet + 192, 3, pX,      out);
    k_conv<true, false><<<gTap,   NTHR, SMEM_BYTES>>>(pU,    Ws + 3*WSTRIDE, gam + 192, bet + 192, 3, nullptr, out);
}